// round 14
// baseline (speedup 1.0000x reference)
#include <cuda_runtime.h>
#include <cstdint>
#include <cstddef>

// Problem constants
#define LNUM 3
#define HDIM 128
#define NHEADS 8
#define HD 16
#define FF 512
#define BSZ 32
#define NN 512
#define ROWS (BSZ*NN)          // 16384
#define NUM_BINS 50
#define KS 17                  // attention K/V smem row stride (R3-proven, conflict-free scalar LDS)

// -------------------- scratch (device globals; no allocation) --------------------
__device__ float g_t0[ROWS*HDIM];
__device__ float g_q [ROWS*HDIM];
__device__ float g_k [ROWS*HDIM];
__device__ float g_v [ROWS*HDIM];
__device__ float g_a [ROWS*HDIM];
__device__ float g_u [ROWS*2*FF];
__device__ float g_g [ROWS*FF];

// -------------------- LayerNorm: one warp per 128-elem row --------------------
__global__ void ln_kernel(const float* __restrict__ x, const float* __restrict__ g,
                          const float* __restrict__ b, float* __restrict__ y)
{
    int warp = threadIdx.x >> 5, lane = threadIdx.x & 31;
    int row  = blockIdx.x * 8 + warp;
    const float4* x4 = (const float4*)(x + (size_t)row * HDIM);
    float4 v = x4[lane];
    float s  = v.x + v.y + v.z + v.w;
    float sq = v.x*v.x + v.y*v.y + v.z*v.z + v.w*v.w;
    #pragma unroll
    for (int o = 16; o > 0; o >>= 1) {
        s  += __shfl_xor_sync(0xffffffffu, s,  o);
        sq += __shfl_xor_sync(0xffffffffu, sq, o);
    }
    float mu  = s * (1.0f/128.0f);
    float var = sq * (1.0f/128.0f) - mu*mu;
    float rs  = rsqrtf(var + 1e-5f);
    float4 gg = ((const float4*)g)[lane];
    float4 bb = ((const float4*)b)[lane];
    float4 o;
    o.x = (v.x - mu) * rs * gg.x + bb.x;
    o.y = (v.y - mu) * rs * gg.y + bb.y;
    o.z = (v.z - mu) * rs * gg.z + bb.z;
    o.w = (v.w - mu) * rs * gg.w + bb.w;
    ((float4*)(y + (size_t)row * HDIM))[lane] = o;
}

// -------------------- helpers: tf32 round-to-nearest --------------------
__device__ __forceinline__ float to_tf32(float x) {
    float r;
    asm("cvt.rna.tf32.f32 %0, %1;" : "=f"(r) : "f"(x));
    return r;
}

// -------------------- tensor-core tf32 GEMM, 3-pass split, 64x128 CTA tile,
// register-double-buffered staging (global loads for slab i+1 overlap compute of slab i) ----
#define TAST 36    // A stride: banks 4g+tg distinct
#define TBST 136   // B stride: 136 mod 32 = 8 -> banks 8tg+g distinct
#define GSM  ((2*64*TAST + 2*32*TBST) * (int)sizeof(float))   // 53248 B
template<bool ADD>
__global__ __launch_bounds__(256)
void gemm_tf32(const float* __restrict__ A, const float* __restrict__ W,
               const float* __restrict__ bias, float* __restrict__ C,
               int N, int K, int lda)
{
    extern __shared__ float sh[];
    float* Ahi = sh;                    // 64*36
    float* Alo = Ahi + 64*TAST;
    float* Bhi = Alo + 64*TAST;         // 32*136
    float* Blo = Bhi + 32*TBST;

    int tid  = threadIdx.x;
    int warp = tid >> 5, lane = tid & 31;
    int wm = warp >> 2, wn = warp & 3;        // 2 x 4 warp grid
    int g  = lane >> 2, tg = lane & 3;        // groupID, thread-in-group
    int m0 = blockIdx.y * 64, n0 = blockIdx.x * 128;

    // per-thread staging coordinates
    int ar[2], ac[2], bk_[4], bc[4];
    #pragma unroll
    for (int it = 0; it < 2; it++) {
        int idx = tid + it*256;
        ar[it] = idx >> 3; ac[it] = idx & 7;
    }
    #pragma unroll
    for (int it = 0; it < 4; it++) {
        int idx = tid + it*256;
        bk_[it] = idx >> 5; bc[it] = idx & 31;
    }

    float acc[2][4][4];
    #pragma unroll
    for (int i = 0; i < 2; i++)
        #pragma unroll
        for (int j = 0; j < 4; j++)
            #pragma unroll
            for (int r = 0; r < 4; r++) acc[i][j][r] = 0.0f;

    // preload slab 0 into registers
    float4 ra[2], rb[4];
    #pragma unroll
    for (int it = 0; it < 2; it++)
        ra[it] = *(const float4*)(A + (size_t)(m0 + ar[it]) * lda + ac[it]*4);
    #pragma unroll
    for (int it = 0; it < 4; it++)
        rb[it] = *(const float4*)(W + (size_t)bk_[it] * N + n0 + bc[it]*4);

    for (int k0 = 0; k0 < K; k0 += 32) {
        // commit current regs to smem (hi = tf32 cvt; lo raw — MMA HW rounds operands on read)
        #pragma unroll
        for (int it = 0; it < 2; it++) {
            int base = ar[it]*TAST + ac[it]*4;
            float h0 = to_tf32(ra[it].x), h1 = to_tf32(ra[it].y),
                  h2 = to_tf32(ra[it].z), h3 = to_tf32(ra[it].w);
            Ahi[base+0] = h0; Ahi[base+1] = h1; Ahi[base+2] = h2; Ahi[base+3] = h3;
            Alo[base+0] = ra[it].x - h0; Alo[base+1] = ra[it].y - h1;
            Alo[base+2] = ra[it].z - h2; Alo[base+3] = ra[it].w - h3;
        }
        #pragma unroll
        for (int it = 0; it < 4; it++) {
            int base = bk_[it]*TBST + bc[it]*4;
            float h0 = to_tf32(rb[it].x), h1 = to_tf32(rb[it].y),
                  h2 = to_tf32(rb[it].z), h3 = to_tf32(rb[it].w);
            Bhi[base+0] = h0; Bhi[base+1] = h1; Bhi[base+2] = h2; Bhi[base+3] = h3;
            Blo[base+0] = rb[it].x - h0; Blo[base+1] = rb[it].y - h1;
            Blo[base+2] = rb[it].z - h2; Blo[base+3] = rb[it].w - h3;
        }
        __syncthreads();

        // prefetch next slab (global latency overlaps the MMA phase below)
        int kn = k0 + 32;
        if (kn < K) {
            #pragma unroll
            for (int it = 0; it < 2; it++)
                ra[it] = *(const float4*)(A + (size_t)(m0 + ar[it]) * lda + kn + ac[it]*4);
            #pragma unroll
            for (int it = 0; it < 4; it++)
                rb[it] = *(const float4*)(W + (size_t)(kn + bk_[it]) * N + n0 + bc[it]*4);
        }

        #pragma unroll
        for (int k8 = 0; k8 < 32; k8 += 8) {
            unsigned bh[4][2], bl[4][2];
            #pragma unroll
            for (int nt = 0; nt < 4; nt++) {
                int nb = wn*32 + nt*8 + g;
                bh[nt][0] = __float_as_uint(Bhi[(k8+tg  )*TBST + nb]);
                bh[nt][1] = __float_as_uint(Bhi[(k8+tg+4)*TBST + nb]);
                bl[nt][0] = __float_as_uint(Blo[(k8+tg  )*TBST + nb]);
                bl[nt][1] = __float_as_uint(Blo[(k8+tg+4)*TBST + nb]);
            }
            #pragma unroll
            for (int mt = 0; mt < 2; mt++) {
                int mb = wm*32 + mt*16;
                unsigned ah[4], al[4];
                ah[0] = __float_as_uint(Ahi[(mb+g  )*TAST + k8+tg  ]);
                ah[1] = __float_as_uint(Ahi[(mb+g+8)*TAST + k8+tg  ]);
                ah[2] = __float_as_uint(Ahi[(mb+g  )*TAST + k8+tg+4]);
                ah[3] = __float_as_uint(Ahi[(mb+g+8)*TAST + k8+tg+4]);
                al[0] = __float_as_uint(Alo[(mb+g  )*TAST + k8+tg  ]);
                al[1] = __float_as_uint(Alo[(mb+g+8)*TAST + k8+tg  ]);
                al[2] = __float_as_uint(Alo[(mb+g  )*TAST + k8+tg+4]);
                al[3] = __float_as_uint(Alo[(mb+g+8)*TAST + k8+tg+4]);
                #pragma unroll
                for (int nt = 0; nt < 4; nt++) {
                    float* d = acc[mt][nt];
                    asm volatile(
                        "mma.sync.aligned.m16n8k8.row.col.f32.tf32.tf32.f32 "
                        "{%0,%1,%2,%3}, {%4,%5,%6,%7}, {%8,%9}, {%0,%1,%2,%3};"
                        : "+f"(d[0]), "+f"(d[1]), "+f"(d[2]), "+f"(d[3])
                        : "r"(ah[0]),"r"(ah[1]),"r"(ah[2]),"r"(ah[3]),
                          "r"(bh[nt][0]),"r"(bh[nt][1]));
                    asm volatile(
                        "mma.sync.aligned.m16n8k8.row.col.f32.tf32.tf32.f32 "
                        "{%0,%1,%2,%3}, {%4,%5,%6,%7}, {%8,%9}, {%0,%1,%2,%3};"
                        : "+f"(d[0]), "+f"(d[1]), "+f"(d[2]), "+f"(d[3])
                        : "r"(al[0]),"r"(al[1]),"r"(al[2]),"r"(al[3]),
                          "r"(bh[nt][0]),"r"(bh[nt][1]));
                    asm volatile(
                        "mma.sync.aligned.m16n8k8.row.col.f32.tf32.tf32.f32 "
                        "{%0,%1,%2,%3}, {%4,%5,%6,%7}, {%8,%9}, {%0,%1,%2,%3};"
                        : "+f"(d[0]), "+f"(d[1]), "+f"(d[2]), "+f"(d[3])
                        : "r"(ah[0]),"r"(ah[1]),"r"(ah[2]),"r"(ah[3]),
                          "r"(bl[nt][0]),"r"(bl[nt][1]));
                }
            }
        }
        __syncthreads();
    }

    // epilogue: c0,c1 -> row g, cols 2tg,2tg+1 ; c2,c3 -> row g+8
    #pragma unroll
    for (int mt = 0; mt < 2; mt++) {
        int r0 = m0 + wm*32 + mt*16 + g;
        #pragma unroll
        for (int nt = 0; nt < 4; nt++) {
            int c = n0 + wn*32 + nt*8 + 2*tg;
            float b0 = __ldg(bias + c), b1 = __ldg(bias + c + 1);
            float v0 = acc[mt][nt][0] + b0, v1 = acc[mt][nt][1] + b1;
            float v2 = acc[mt][nt][2] + b0, v3 = acc[mt][nt][3] + b1;
            float* p0 = C + (size_t)r0 * N + c;
            float* p1 = C + (size_t)(r0 + 8) * N + c;
            if (ADD) {
                float2 o0 = *(float2*)p0, o1 = *(float2*)p1;
                v0 += o0.x; v1 += o0.y; v2 += o1.x; v3 += o1.y;
            }
            *(float2*)p0 = make_float2(v0, v1);
            *(float2*)p1 = make_float2(v2, v3);
        }
    }
}

// -------------------- fused attention (R11, verbatim): scalar-LDS, 2 rows share each K/V read,
// single pass without max-subtraction (scores bounded; masked keys -> expf(-1e9)=0) ----------
__global__ __launch_bounds__(512)
void attn_kernel(const float* __restrict__ Q, const float* __restrict__ Kt,
                 const float* __restrict__ V, const float* __restrict__ dist,
                 const unsigned int* __restrict__ mask,   // 4-byte elements; nonzero = masked
                 const float* __restrict__ demb,   // [50,8] for this layer
                 const float* __restrict__ abias,  // [8]    for this layer
                 float* __restrict__ out)
{
    extern __shared__ float sm[];
    float* Ksh = sm;                 // 512*17
    float* Vsh = Ksh + NN*KS;        // 512*17
    float* mb  = Vsh + NN*KS;        // 512
    float* de  = mb + NN;            // 64

    int b = blockIdx.x >> 3, h = blockIdx.x & 7;
    int tid = threadIdx.x;

    for (int idx = tid; idx < NN*4; idx += 512) {
        int r = idx >> 2, c = idx & 3;
        size_t goff = ((size_t)b*NN + r) * HDIM + h*HD + c*4;
        float4 kv = *(const float4*)(Kt + goff);
        Ksh[r*KS + c*4+0] = kv.x; Ksh[r*KS + c*4+1] = kv.y;
        Ksh[r*KS + c*4+2] = kv.z; Ksh[r*KS + c*4+3] = kv.w;
        float4 vv = *(const float4*)(V + goff);
        Vsh[r*KS + c*4+0] = vv.x; Vsh[r*KS + c*4+1] = vv.y;
        Vsh[r*KS + c*4+2] = vv.z; Vsh[r*KS + c*4+3] = vv.w;
    }
    if (tid < NN)  mb[tid] = (mask[(size_t)b*NN + tid] != 0u) ? -1e9f : 0.0f;
    if (tid < NUM_BINS) de[tid] = demb[tid*NHEADS + h];
    float ab = abias[h];
    __syncthreads();

    int warp = tid >> 5, lane = tid & 31;
    int qbase = blockIdx.y * 64 + warp * 4;

    for (int rr = 0; rr < 2; rr++) {
        int q0 = qbase + rr*2;
        int q1 = q0 + 1;
        const float* qp0 = Q + ((size_t)b*NN + q0) * HDIM + h*HD;
        const float* qp1 = Q + ((size_t)b*NN + q1) * HDIM + h*HD;
        float qv0[HD], qv1[HD];
        #pragma unroll
        for (int d = 0; d < HD; d++) { qv0[d] = __ldg(qp0 + d); qv1[d] = __ldg(qp1 + d); }

        const float* drow0 = dist + ((size_t)b*NN + q0) * NN;
        const float* drow1 = dist + ((size_t)b*NN + q1) * NN;

        float ssum0 = 0.0f, ssum1 = 0.0f;
        float acc0[HD], acc1[HD];
        #pragma unroll
        for (int d = 0; d < HD; d++) { acc0[d] = 0.0f; acc1[d] = 0.0f; }

        #pragma unroll
        for (int kk = 0; kk < 16; kk++) {
            int k = kk*32 + lane;
            float dv0 = drow0[k];
            float dv1 = drow1[k];
            int bin0 = (int)(dv0 * 10.0f); bin0 = bin0 < 0 ? 0 : (bin0 > NUM_BINS-1 ? NUM_BINS-1 : bin0);
            int bin1 = (int)(dv1 * 10.0f); bin1 = bin1 < 0 ? 0 : (bin1 > NUM_BINS-1 ? NUM_BINS-1 : bin1);
            float extra = ab + mb[k];
            float dot0 = 0.0f, dot1 = 0.0f;
            #pragma unroll
            for (int d = 0; d < HD; d++) {
                float kvv = Ksh[k*KS + d];           // one LDS feeds both rows
                dot0 = fmaf(qv0[d], kvv, dot0);
                dot1 = fmaf(qv1[d], kvv, dot1);
            }
            float p0 = __expf(dot0 * 0.25f + de[bin0] + extra);
            float p1 = __expf(dot1 * 0.25f + de[bin1] + extra);
            ssum0 += p0; ssum1 += p1;
            #pragma unroll
            for (int d = 0; d < HD; d++) {
                float vvv = Vsh[k*KS + d];           // one LDS feeds both rows
                acc0[d] = fmaf(p0, vvv, acc0[d]);
                acc1[d] = fmaf(p1, vvv, acc1[d]);
            }
        }

        #pragma unroll
        for (int o = 16; o > 0; o >>= 1) {
            ssum0 += __shfl_xor_sync(0xffffffffu, ssum0, o);
            ssum1 += __shfl_xor_sync(0xffffffffu, ssum1, o);
            #pragma unroll
            for (int d = 0; d < HD; d++) {
                acc0[d] += __shfl_xor_sync(0xffffffffu, acc0[d], o);
                acc1[d] += __shfl_xor_sync(0xffffffffu, acc1[d], o);
            }
        }
        if (lane == 0) {
            float inv0 = 1.0f / ssum0;
            float inv1 = 1.0f / ssum1;
            float4* o0 = (float4*)(out + ((size_t)b*NN + q0) * HDIM + h*HD);
            float4* o1 = (float4*)(out + ((size_t)b*NN + q1) * HDIM + h*HD);
            o0[0] = make_float4(acc0[0]*inv0,  acc0[1]*inv0,  acc0[2]*inv0,  acc0[3]*inv0);
            o0[1] = make_float4(acc0[4]*inv0,  acc0[5]*inv0,  acc0[6]*inv0,  acc0[7]*inv0);
            o0[2] = make_float4(acc0[8]*inv0,  acc0[9]*inv0,  acc0[10]*inv0, acc0[11]*inv0);
            o0[3] = make_float4(acc0[12]*inv0, acc0[13]*inv0, acc0[14]*inv0, acc0[15]*inv0);
            o1[0] = make_float4(acc1[0]*inv1,  acc1[1]*inv1,  acc1[2]*inv1,  acc1[3]*inv1);
            o1[1] = make_float4(acc1[4]*inv1,  acc1[5]*inv1,  acc1[6]*inv1,  acc1[7]*inv1);
            o1[2] = make_float4(acc1[8]*inv1,  acc1[9]*inv1,  acc1[10]*inv1, acc1[11]*inv1);
            o1[3] = make_float4(acc1[12]*inv1, acc1[13]*inv1, acc1[14]*inv1, acc1[15]*inv1);
        }
    }
}
#define ATTN_SMEM ((2*NN*KS + NN + 64) * (int)sizeof(float))

// -------------------- GLU --------------------
__global__ void glu_kernel(const float* __restrict__ u, float* __restrict__ g, int total4)
{
    int idx = blockIdx.x * blockDim.x + threadIdx.x;
    if (idx >= total4) return;
    int r = idx >> 7, j4 = idx & 127;
    float4 a = *(const float4*)(u + (size_t)r * (2*FF) + j4*4);
    float4 c = *(const float4*)(u + (size_t)r * (2*FF) + FF + j4*4);
    float4 o;
    o.x = a.x / (1.0f + __expf(-c.x));
    o.y = a.y / (1.0f + __expf(-c.y));
    o.z = a.z / (1.0f + __expf(-c.z));
    o.w = a.w / (1.0f + __expf(-c.w));
    *(float4*)(g + (size_t)r * FF + j4*4) = o;
}

// -------------------- launch --------------------
extern "C" void kernel_launch(void* const* d_in, const int* in_sizes, int n_in,
                              void* d_out, int out_size)
{
    const float*        x    = (const float*)d_in[0];
    const float*        dist = (const float*)d_in[1];
    const unsigned int* mask = (const unsigned int*)d_in[2];  // bool widened to 4-byte dtype
    const float* Wq  = (const float*)d_in[3];
    const float* bq  = (const float*)d_in[4];
    const float* Wk  = (const float*)d_in[5];
    const float* bk  = (const float*)d_in[6];
    const float* Wv  = (const float*)d_in[7];
    const float* bv  = (const float*)d_in[8];
    const float* Wo  = (const float*)d_in[9];
    const float* bo  = (const float*)d_in[10];
    const float* demb  = (const float*)d_in[11];
    const float* abias = (const float*)d_in[12];
    const float* g1  = (const float*)d_in[13];
    const float* b1  = (const float*)d_in[14];
    const float* g2  = (const float*)d_in[15];
    const float* b2  = (const float*)d_in[16];
    const float* Wf1 = (const float*)d_in[17];
    const float* bf1 = (const float*)d_in[18];
    const float* Wf2 = (const float*)d_in[19];
    const float* bf2 = (const float*)d_in[20];
    float* h = (float*)d_out;

    float *t0, *q, *k, *v, *a, *u, *g;
    cudaGetSymbolAddress((void**)&t0, g_t0);
    cudaGetSymbolAddress((void**)&q,  g_q);
    cudaGetSymbolAddress((void**)&k,  g_k);
    cudaGetSymbolAddress((void**)&v,  g_v);
    cudaGetSymbolAddress((void**)&a,  g_a);
    cudaGetSymbolAddress((void**)&u,  g_u);
    cudaGetSymbolAddress((void**)&g,  g_g);

    cudaFuncSetAttribute(attn_kernel, cudaFuncAttributeMaxDynamicSharedMemorySize, ATTN_SMEM);
    cudaFuncSetAttribute(gemm_tf32<false>, cudaFuncAttributeMaxDynamicSharedMemorySize, GSM);
    cudaFuncSetAttribute(gemm_tf32<true>,  cudaFuncAttributeMaxDynamicSharedMemorySize, GSM);

    cudaMemcpyAsync(h, x, sizeof(float)*(size_t)ROWS*HDIM, cudaMemcpyDeviceToDevice, 0);

    for (int l = 0; l < LNUM; l++) {
        ln_kernel<<<ROWS/8, 256>>>(h, g1 + l*HDIM, b1 + l*HDIM, t0);

        gemm_tf32<false><<<dim3(HDIM/128, ROWS/64), 256, GSM>>>(t0, Wq + (size_t)l*HDIM*HDIM, bq + l*HDIM, q, HDIM, HDIM, HDIM);
        gemm_tf32<false><<<dim3(HDIM/128, ROWS/64), 256, GSM>>>(t0, Wk + (size_t)l*HDIM*HDIM, bk + l*HDIM, k, HDIM, HDIM, HDIM);
        gemm_tf32<false><<<dim3(HDIM/128, ROWS/64), 256, GSM>>>(t0, Wv + (size_t)l*HDIM*HDIM, bv + l*HDIM, v, HDIM, HDIM, HDIM);

        attn_kernel<<<dim3(BSZ*NHEADS, NN/64), 512, ATTN_SMEM>>>(q, k, v, dist, mask,
                                                                 demb + l*NUM_BINS*NHEADS,
                                                                 abias + l*NHEADS, a);

        gemm_tf32<true><<<dim3(HDIM/128, ROWS/64), 256, GSM>>>(a, Wo + (size_t)l*HDIM*HDIM, bo + l*HDIM, h, HDIM, HDIM, HDIM);

        ln_kernel<<<ROWS/8, 256>>>(h, g2 + l*HDIM, b2 + l*HDIM, t0);

        // FF1: t0[16384,128] @ Wf1[128,1024] -> u
        gemm_tf32<false><<<dim3((2*FF)/128, ROWS/64), 256, GSM>>>(t0, Wf1 + (size_t)l*HDIM*2*FF, bf1 + l*2*FF, u, 2*FF, HDIM, HDIM);

        glu_kernel<<<(ROWS*FF/4 + 255)/256, 256>>>(u, g, ROWS*FF/4);

        // FF2: h += g[16384,512] @ Wf2[512,128] + bf2
        gemm_tf32<true><<<dim3(HDIM/128, ROWS/64), 256, GSM>>>(g, Wf2 + (size_t)l*FF*HDIM, bf2 + l*HDIM, h, HDIM, FF, FF);
    }
}

// round 15
// speedup vs baseline: 1.0774x; 1.0774x over previous
#include <cuda_runtime.h>
#include <cstdint>
#include <cstddef>

// Problem constants
#define LNUM 3
#define HDIM 128
#define NHEADS 8
#define HD 16
#define FF 512
#define BSZ 32
#define NN 512
#define ROWS (BSZ*NN)          // 16384
#define NUM_BINS 50
#define KS 17                  // attention K/V smem row stride (R3-proven, conflict-free scalar LDS)

// -------------------- scratch (device globals; no allocation) --------------------
__device__ float g_t0[ROWS*HDIM];
__device__ float g_q [ROWS*HDIM];
__device__ float g_k [ROWS*HDIM];
__device__ float g_v [ROWS*HDIM];
__device__ float g_a [ROWS*HDIM];
__device__ float g_u [ROWS*2*FF];
__device__ signed char g_bins[(size_t)BSZ*NN*NN];   // 8.4MB, layer-independent

// -------------------- bins precompute: bin = clip((int)(dist*10), 0, 49), int8 --------------------
__global__ void bins_kernel(const float* __restrict__ dist, signed char* __restrict__ bins, int n4)
{
    int idx = blockIdx.x * blockDim.x + threadIdx.x;
    if (idx >= n4) return;
    float4 d = ((const float4*)dist)[idx];
    int b0 = (int)(d.x * 10.0f); b0 = b0 < 0 ? 0 : (b0 > NUM_BINS-1 ? NUM_BINS-1 : b0);
    int b1 = (int)(d.y * 10.0f); b1 = b1 < 0 ? 0 : (b1 > NUM_BINS-1 ? NUM_BINS-1 : b1);
    int b2 = (int)(d.z * 10.0f); b2 = b2 < 0 ? 0 : (b2 > NUM_BINS-1 ? NUM_BINS-1 : b2);
    int b3 = (int)(d.w * 10.0f); b3 = b3 < 0 ? 0 : (b3 > NUM_BINS-1 ? NUM_BINS-1 : b3);
    char4 c; c.x = (signed char)b0; c.y = (signed char)b1; c.z = (signed char)b2; c.w = (signed char)b3;
    ((char4*)bins)[idx] = c;
}

// -------------------- LayerNorm: one warp per 128-elem row --------------------
__global__ void ln_kernel(const float* __restrict__ x, const float* __restrict__ g,
                          const float* __restrict__ b, float* __restrict__ y)
{
    int warp = threadIdx.x >> 5, lane = threadIdx.x & 31;
    int row  = blockIdx.x * 8 + warp;
    const float4* x4 = (const float4*)(x + (size_t)row * HDIM);
    float4 v = x4[lane];
    float s  = v.x + v.y + v.z + v.w;
    float sq = v.x*v.x + v.y*v.y + v.z*v.z + v.w*v.w;
    #pragma unroll
    for (int o = 16; o > 0; o >>= 1) {
        s  += __shfl_xor_sync(0xffffffffu, s,  o);
        sq += __shfl_xor_sync(0xffffffffu, sq, o);
    }
    float mu  = s * (1.0f/128.0f);
    float var = sq * (1.0f/128.0f) - mu*mu;
    float rs  = rsqrtf(var + 1e-5f);
    float4 gg = ((const float4*)g)[lane];
    float4 bb = ((const float4*)b)[lane];
    float4 o;
    o.x = (v.x - mu) * rs * gg.x + bb.x;
    o.y = (v.y - mu) * rs * gg.y + bb.y;
    o.z = (v.z - mu) * rs * gg.z + bb.z;
    o.w = (v.w - mu) * rs * gg.w + bb.w;
    ((float4*)(y + (size_t)row * HDIM))[lane] = o;
}

// -------------------- helpers --------------------
__device__ __forceinline__ float to_tf32(float x) {
    float r;
    asm("cvt.rna.tf32.f32 %0, %1;" : "=f"(r) : "f"(x));
    return r;
}

// -------------------- tensor-core tf32 GEMM body (R14-proven), optional fused GLU on A --------------------
#define TAST 36    // A stride: banks 4g+tg distinct
#define TBST 136   // B stride: 136 mod 32 = 8 -> banks 8tg+g distinct
#define GSM  ((2*64*TAST + 2*32*TBST) * (int)sizeof(float))   // 53248 B
template<bool ADD, bool GLU>
__device__ __forceinline__
void gemm_body(const float* __restrict__ A, const float* __restrict__ W,
               const float* __restrict__ bias, float* __restrict__ C,
               int N, int K, int lda, int m0, int n0)
{
    extern __shared__ float sh[];
    float* Ahi = sh;                    // 64*36
    float* Alo = Ahi + 64*TAST;
    float* Bhi = Alo + 64*TAST;         // 32*136
    float* Blo = Bhi + 32*TBST;

    int tid  = threadIdx.x;
    int warp = tid >> 5, lane = tid & 31;
    int wm = warp >> 2, wn = warp & 3;        // 2 x 4 warp grid
    int g  = lane >> 2, tg = lane & 3;        // groupID, thread-in-group

    // per-thread staging coordinates
    int ar[2], ac[2], bk_[4], bc[4];
    #pragma unroll
    for (int it = 0; it < 2; it++) {
        int idx = tid + it*256;
        ar[it] = idx >> 3; ac[it] = idx & 7;
    }
    #pragma unroll
    for (int it = 0; it < 4; it++) {
        int idx = tid + it*256;
        bk_[it] = idx >> 5; bc[it] = idx & 31;
    }

    float acc[2][4][4];
    #pragma unroll
    for (int i = 0; i < 2; i++)
        #pragma unroll
        for (int j = 0; j < 4; j++)
            #pragma unroll
            for (int r = 0; r < 4; r++) acc[i][j][r] = 0.0f;

    // preload slab 0 into registers
    float4 ra[2], rb[4], rc[2];
    #pragma unroll
    for (int it = 0; it < 2; it++) {
        const float* ap = A + (size_t)(m0 + ar[it]) * lda + ac[it]*4;
        ra[it] = *(const float4*)ap;
        if (GLU) rc[it] = *(const float4*)(ap + FF);
    }
    #pragma unroll
    for (int it = 0; it < 4; it++)
        rb[it] = *(const float4*)(W + (size_t)bk_[it] * N + n0 + bc[it]*4);

    for (int k0 = 0; k0 < K; k0 += 32) {
        // commit regs to smem (GLU: a *= sigmoid(gate); hi = tf32 cvt; lo raw)
        #pragma unroll
        for (int it = 0; it < 2; it++) {
            float4 av = ra[it];
            if (GLU) {
                av.x /= (1.0f + __expf(-rc[it].x));
                av.y /= (1.0f + __expf(-rc[it].y));
                av.z /= (1.0f + __expf(-rc[it].z));
                av.w /= (1.0f + __expf(-rc[it].w));
            }
            int base = ar[it]*TAST + ac[it]*4;
            float h0 = to_tf32(av.x), h1 = to_tf32(av.y), h2 = to_tf32(av.z), h3 = to_tf32(av.w);
            Ahi[base+0] = h0; Ahi[base+1] = h1; Ahi[base+2] = h2; Ahi[base+3] = h3;
            Alo[base+0] = av.x - h0; Alo[base+1] = av.y - h1;
            Alo[base+2] = av.z - h2; Alo[base+3] = av.w - h3;
        }
        #pragma unroll
        for (int it = 0; it < 4; it++) {
            int base = bk_[it]*TBST + bc[it]*4;
            float h0 = to_tf32(rb[it].x), h1 = to_tf32(rb[it].y),
                  h2 = to_tf32(rb[it].z), h3 = to_tf32(rb[it].w);
            Bhi[base+0] = h0; Bhi[base+1] = h1; Bhi[base+2] = h2; Bhi[base+3] = h3;
            Blo[base+0] = rb[it].x - h0; Blo[base+1] = rb[it].y - h1;
            Blo[base+2] = rb[it].z - h2; Blo[base+3] = rb[it].w - h3;
        }
        __syncthreads();

        // prefetch next slab (latency overlaps MMA phase)
        int kn = k0 + 32;
        if (kn < K) {
            #pragma unroll
            for (int it = 0; it < 2; it++) {
                const float* ap = A + (size_t)(m0 + ar[it]) * lda + kn + ac[it]*4;
                ra[it] = *(const float4*)ap;
                if (GLU) rc[it] = *(const float4*)(ap + FF);
            }
            #pragma unroll
            for (int it = 0; it < 4; it++)
                rb[it] = *(const float4*)(W + (size_t)(kn + bk_[it]) * N + n0 + bc[it]*4);
        }

        #pragma unroll
        for (int k8 = 0; k8 < 32; k8 += 8) {
            unsigned bh[4][2], bl[4][2];
            #pragma unroll
            for (int nt = 0; nt < 4; nt++) {
                int nb = wn*32 + nt*8 + g;
                bh[nt][0] = __float_as_uint(Bhi[(k8+tg  )*TBST + nb]);
                bh[nt][1] = __float_as_uint(Bhi[(k8+tg+4)*TBST + nb]);
                bl[nt][0] = __float_as_uint(Blo[(k8+tg  )*TBST + nb]);
                bl[nt][1] = __float_as_uint(Blo[(k8+tg+4)*TBST + nb]);
            }
            #pragma unroll
            for (int mt = 0; mt < 2; mt++) {
                int mb = wm*32 + mt*16;
                unsigned ah[4], al[4];
                ah[0] = __float_as_uint(Ahi[(mb+g  )*TAST + k8+tg  ]);
                ah[1] = __float_as_uint(Ahi[(mb+g+8)*TAST + k8+tg  ]);
                ah[2] = __float_as_uint(Ahi[(mb+g  )*TAST + k8+tg+4]);
                ah[3] = __float_as_uint(Ahi[(mb+g+8)*TAST + k8+tg+4]);
                al[0] = __float_as_uint(Alo[(mb+g  )*TAST + k8+tg  ]);
                al[1] = __float_as_uint(Alo[(mb+g+8)*TAST + k8+tg  ]);
                al[2] = __float_as_uint(Alo[(mb+g  )*TAST + k8+tg+4]);
                al[3] = __float_as_uint(Alo[(mb+g+8)*TAST + k8+tg+4]);
                #pragma unroll
                for (int nt = 0; nt < 4; nt++) {
                    float* d = acc[mt][nt];
                    asm volatile(
                        "mma.sync.aligned.m16n8k8.row.col.f32.tf32.tf32.f32 "
                        "{%0,%1,%2,%3}, {%4,%5,%6,%7}, {%8,%9}, {%0,%1,%2,%3};"
                        : "+f"(d[0]), "+f"(d[1]), "+f"(d[2]), "+f"(d[3])
                        : "r"(ah[0]),"r"(ah[1]),"r"(ah[2]),"r"(ah[3]),
                          "r"(bh[nt][0]),"r"(bh[nt][1]));
                    asm volatile(
                        "mma.sync.aligned.m16n8k8.row.col.f32.tf32.tf32.f32 "
                        "{%0,%1,%2,%3}, {%4,%5,%6,%7}, {%8,%9}, {%0,%1,%2,%3};"
                        : "+f"(d[0]), "+f"(d[1]), "+f"(d[2]), "+f"(d[3])
                        : "r"(al[0]),"r"(al[1]),"r"(al[2]),"r"(al[3]),
                          "r"(bh[nt][0]),"r"(bh[nt][1]));
                    asm volatile(
                        "mma.sync.aligned.m16n8k8.row.col.f32.tf32.tf32.f32 "
                        "{%0,%1,%2,%3}, {%4,%5,%6,%7}, {%8,%9}, {%0,%1,%2,%3};"
                        : "+f"(d[0]), "+f"(d[1]), "+f"(d[2]), "+f"(d[3])
                        : "r"(ah[0]),"r"(ah[1]),"r"(ah[2]),"r"(ah[3]),
                          "r"(bl[nt][0]),"r"(bl[nt][1]));
                }
            }
        }
        __syncthreads();
    }

    #pragma unroll
    for (int mt = 0; mt < 2; mt++) {
        int r0 = m0 + wm*32 + mt*16 + g;
        #pragma unroll
        for (int nt = 0; nt < 4; nt++) {
            int c = n0 + wn*32 + nt*8 + 2*tg;
            float b0 = __ldg(bias + c), b1 = __ldg(bias + c + 1);
            float v0 = acc[mt][nt][0] + b0, v1 = acc[mt][nt][1] + b1;
            float v2 = acc[mt][nt][2] + b0, v3 = acc[mt][nt][3] + b1;
            float* p0 = C + (size_t)r0 * N + c;
            float* p1 = C + (size_t)(r0 + 8) * N + c;
            if (ADD) {
                float2 o0 = *(float2*)p0, o1 = *(float2*)p1;
                v0 += o0.x; v1 += o0.y; v2 += o1.x; v3 += o1.y;
            }
            *(float2*)p0 = make_float2(v0, v1);
            *(float2*)p1 = make_float2(v2, v3);
        }
    }
}

template<bool ADD>
__global__ __launch_bounds__(256)
void gemm_std(const float* __restrict__ A, const float* __restrict__ W,
              const float* __restrict__ bias, float* __restrict__ C,
              int N, int K, int lda)
{
    gemm_body<ADD, false>(A, W, bias, C, N, K, lda, blockIdx.y * 64, blockIdx.x * 128);
}

// fused Q/K/V: blockIdx.z selects projection
__global__ __launch_bounds__(256)
void gemm_qkv(const float* __restrict__ A,
              const float* __restrict__ Wq, const float* __restrict__ Wk, const float* __restrict__ Wv,
              const float* __restrict__ bq, const float* __restrict__ bk, const float* __restrict__ bv,
              float* __restrict__ Cq, float* __restrict__ Ck, float* __restrict__ Cv)
{
    int z = blockIdx.z;
    const float* W = (z == 0) ? Wq : (z == 1) ? Wk : Wv;
    const float* b = (z == 0) ? bq : (z == 1) ? bk : bv;
    float*       C = (z == 0) ? Cq : (z == 1) ? Ck : Cv;
    gemm_body<false, false>(A, W, b, C, HDIM, HDIM, HDIM, blockIdx.y * 64, 0);
}

// FF2 with fused GLU on A-staging: h += glu(u) @ Wf2 + bf2
__global__ __launch_bounds__(256)
void gemm_ff2(const float* __restrict__ u, const float* __restrict__ W,
              const float* __restrict__ bias, float* __restrict__ C)
{
    gemm_body<true, true>(u, W, bias, C, HDIM, FF, 2*FF, blockIdx.y * 64, 0);
}

// -------------------- fused attention (R11 hot loop; int8 bins input) --------------------
__global__ __launch_bounds__(512)
void attn_kernel(const float* __restrict__ Q, const float* __restrict__ Kt,
                 const float* __restrict__ V, const signed char* __restrict__ bins,
                 const unsigned int* __restrict__ mask,   // 4-byte elements; nonzero = masked
                 const float* __restrict__ demb,   // [50,8] for this layer
                 const float* __restrict__ abias,  // [8]    for this layer
                 float* __restrict__ out)
{
    extern __shared__ float sm[];
    float* Ksh = sm;                 // 512*17
    float* Vsh = Ksh + NN*KS;        // 512*17
    float* mb  = Vsh + NN*KS;        // 512
    float* de  = mb + NN;            // 64

    int b = blockIdx.x >> 3, h = blockIdx.x & 7;
    int tid = threadIdx.x;

    for (int idx = tid; idx < NN*4; idx += 512) {
        int r = idx >> 2, c = idx & 3;
        size_t goff = ((size_t)b*NN + r) * HDIM + h*HD + c*4;
        float4 kv = *(const float4*)(Kt + goff);
        Ksh[r*KS + c*4+0] = kv.x; Ksh[r*KS + c*4+1] = kv.y;
        Ksh[r*KS + c*4+2] = kv.z; Ksh[r*KS + c*4+3] = kv.w;
        float4 vv = *(const float4*)(V + goff);
        Vsh[r*KS + c*4+0] = vv.x; Vsh[r*KS + c*4+1] = vv.y;
        Vsh[r*KS + c*4+2] = vv.z; Vsh[r*KS + c*4+3] = vv.w;
    }
    if (tid < NN)  mb[tid] = (mask[(size_t)b*NN + tid] != 0u) ? -1e9f : 0.0f;
    if (tid < NUM_BINS) de[tid] = demb[tid*NHEADS + h];
    float ab = abias[h];
    __syncthreads();

    int warp = tid >> 5, lane = tid & 31;
    int qbase = blockIdx.y * 64 + warp * 4;

    for (int rr = 0; rr < 2; rr++) {
        int q0 = qbase + rr*2;
        int q1 = q0 + 1;
        const float* qp0 = Q + ((size_t)b*NN + q0) * HDIM + h*HD;
        const float* qp1 = Q + ((size_t)b*NN + q1) * HDIM + h*HD;
        float qv0[HD], qv1[HD];
        #pragma unroll
        for (int d = 0; d < HD; d++) { qv0[d] = __ldg(qp0 + d); qv1[d] = __ldg(qp1 + d); }

        const signed char* brow0 = bins + ((size_t)b*NN + q0) * NN;
        const signed char* brow1 = bins + ((size_t)b*NN + q1) * NN;

        float ssum0 = 0.0f, ssum1 = 0.0f;
        float acc0[HD], acc1[HD];
        #pragma unroll
        for (int d = 0; d < HD; d++) { acc0[d] = 0.0f; acc1[d] = 0.0f; }

        #pragma unroll
        for (int kk = 0; kk < 16; kk++) {
            int k = kk*32 + lane;
            int bin0 = brow0[k];
            int bin1 = brow1[k];
            float extra = ab + mb[k];
            float dot0 = 0.0f, dot1 = 0.0f;
            #pragma unroll
            for (int d = 0; d < HD; d++) {
                float kvv = Ksh[k*KS + d];           // one LDS feeds both rows
                dot0 = fmaf(qv0[d], kvv, dot0);
                dot1 = fmaf(qv1[d], kvv, dot1);
            }
            float p0 = __expf(dot0 * 0.25f + de[bin0] + extra);
            float p1 = __expf(dot1 * 0.25f + de[bin1] + extra);
            ssum0 += p0; ssum1 += p1;
            #pragma unroll
            for (int d = 0; d < HD; d++) {
                float vvv = Vsh[k*KS + d];           // one LDS feeds both rows
                acc0[d] = fmaf(p0, vvv, acc0[d]);
                acc1[d] = fmaf(p1, vvv, acc1[d]);
            }
        }

        #pragma unroll
        for (int o = 16; o > 0; o >>= 1) {
            ssum0 += __shfl_xor_sync(0xffffffffu, ssum0, o);
            ssum1 += __shfl_xor_sync(0xffffffffu, ssum1, o);
            #pragma unroll
            for (int d = 0; d < HD; d++) {
                acc0[d] += __shfl_xor_sync(0xffffffffu, acc0[d], o);
                acc1[d] += __shfl_xor_sync(0xffffffffu, acc1[d], o);
            }
        }
        if (lane == 0) {
            float inv0 = 1.0f / ssum0;
            float inv1 = 1.0f / ssum1;
            float4* o0 = (float4*)(out + ((size_t)b*NN + q0) * HDIM + h*HD);
            float4* o1 = (float4*)(out + ((size_t)b*NN + q1) * HDIM + h*HD);
            o0[0] = make_float4(acc0[0]*inv0,  acc0[1]*inv0,  acc0[2]*inv0,  acc0[3]*inv0);
            o0[1] = make_float4(acc0[4]*inv0,  acc0[5]*inv0,  acc0[6]*inv0,  acc0[7]*inv0);
            o0[2] = make_float4(acc0[8]*inv0,  acc0[9]*inv0,  acc0[10]*inv0, acc0[11]*inv0);
            o0[3] = make_float4(acc0[12]*inv0, acc0[13]*inv0, acc0[14]*inv0, acc0[15]*inv0);
            o1[0] = make_float4(acc1[0]*inv1,  acc1[1]*inv1,  acc1[2]*inv1,  acc1[3]*inv1);
            o1[1] = make_float4(acc1[4]*inv1,  acc1[5]*inv1,  acc1[6]*inv1,  acc1[7]*inv1);
            o1[2] = make_float4(acc1[8]*inv1,  acc1[9]*inv1,  acc1[10]*inv1, acc1[11]*inv1);
            o1[3] = make_float4(acc1[12]*inv1, acc1[13]*inv1, acc1[14]*inv1, acc1[15]*inv1);
        }
    }
}
#define ATTN_SMEM ((2*NN*KS + NN + 64) * (int)sizeof(float))

// -------------------- launch --------------------
extern "C" void kernel_launch(void* const* d_in, const int* in_sizes, int n_in,
                              void* d_out, int out_size)
{
    const float*        x    = (const float*)d_in[0];
    const float*        dist = (const float*)d_in[1];
    const unsigned int* mask = (const unsigned int*)d_in[2];  // bool widened to 4-byte dtype
    const float* Wq  = (const float*)d_in[3];
    const float* bq  = (const float*)d_in[4];
    const float* Wk  = (const float*)d_in[5];
    const float* bk  = (const float*)d_in[6];
    const float* Wv  = (const float*)d_in[7];
    const float* bv  = (const float*)d_in[8];
    const float* Wo  = (const float*)d_in[9];
    const float* bo  = (const float*)d_in[10];
    const float* demb  = (const float*)d_in[11];
    const float* abias = (const float*)d_in[12];
    const float* g1  = (const float*)d_in[13];
    const float* b1  = (const float*)d_in[14];
    const float* g2  = (const float*)d_in[15];
    const float* b2  = (const float*)d_in[16];
    const float* Wf1 = (const float*)d_in[17];
    const float* bf1 = (const float*)d_in[18];
    const float* Wf2 = (const float*)d_in[19];
    const float* bf2 = (const float*)d_in[20];
    float* h = (float*)d_out;

    float *t0, *q, *k, *v, *a, *u;
    signed char* bins;
    cudaGetSymbolAddress((void**)&t0, g_t0);
    cudaGetSymbolAddress((void**)&q,  g_q);
    cudaGetSymbolAddress((void**)&k,  g_k);
    cudaGetSymbolAddress((void**)&v,  g_v);
    cudaGetSymbolAddress((void**)&a,  g_a);
    cudaGetSymbolAddress((void**)&u,  g_u);
    cudaGetSymbolAddress((void**)&bins, g_bins);

    cudaFuncSetAttribute(attn_kernel, cudaFuncAttributeMaxDynamicSharedMemorySize, ATTN_SMEM);
    cudaFuncSetAttribute(gemm_std<false>, cudaFuncAttributeMaxDynamicSharedMemorySize, GSM);
    cudaFuncSetAttribute(gemm_std<true>,  cudaFuncAttributeMaxDynamicSharedMemorySize, GSM);
    cudaFuncSetAttribute(gemm_qkv,        cudaFuncAttributeMaxDynamicSharedMemorySize, GSM);
    cudaFuncSetAttribute(gemm_ff2,        cudaFuncAttributeMaxDynamicSharedMemorySize, GSM);

    cudaMemcpyAsync(h, x, sizeof(float)*(size_t)ROWS*HDIM, cudaMemcpyDeviceToDevice, 0);

    // bins are layer-independent: compute once per launch
    int n4 = BSZ*NN*NN/4;
    bins_kernel<<<(n4 + 255)/256, 256>>>(dist, bins, n4);

    for (int l = 0; l < LNUM; l++) {
        ln_kernel<<<ROWS/8, 256>>>(h, g1 + l*HDIM, b1 + l*HDIM, t0);

        gemm_qkv<<<dim3(1, ROWS/64, 3), 256, GSM>>>(t0,
            Wq + (size_t)l*HDIM*HDIM, Wk + (size_t)l*HDIM*HDIM, Wv + (size_t)l*HDIM*HDIM,
            bq + l*HDIM, bk + l*HDIM, bv + l*HDIM, q, k, v);

        attn_kernel<<<dim3(BSZ*NHEADS, NN/64), 512, ATTN_SMEM>>>(q, k, v, bins, mask,
                                                                 demb + l*NUM_BINS*NHEADS,
                                                                 abias + l*NHEADS, a);

        gemm_std<true><<<dim3(1, ROWS/64), 256, GSM>>>(a, Wo + (size_t)l*HDIM*HDIM, bo + l*HDIM, h, HDIM, HDIM, HDIM);

        ln_kernel<<<ROWS/8, 256>>>(h, g2 + l*HDIM, b2 + l*HDIM, t0);

        // FF1: t0[16384,128] @ Wf1[128,1024] -> u
        gemm_std<false><<<dim3((2*FF)/128, ROWS/64), 256, GSM>>>(t0, Wf1 + (size_t)l*HDIM*2*FF, bf1 + l*2*FF, u, 2*FF, HDIM, HDIM);

        // FF2 with fused GLU: h += glu(u) @ Wf2 + bf2
        gemm_ff2<<<dim3(1, ROWS/64), 256, GSM>>>(u, Wf2 + (size_t)l*FF*HDIM, bf2 + l*HDIM, h);
    }
}